// round 9
// baseline (speedup 1.0000x reference)
#include <cuda_runtime.h>
#include <cuda_bf16.h>
#include <math.h>
#include <stdint.h>

// ---------------------------------------------------------------------------
// SupConLossWithPrototype via mma.sync bf16, MUFU exp epilogue.
//   3-kernel pipeline: prep (flags+convert+compact+g, grid-sync'd),
//   mma_expsum (2 CTAs/SM), finalize (+fused final reduce).
// ---------------------------------------------------------------------------

#define MAXM 8192
#define NCHUNK 9
#define LOG2E5 7.2134752044448170f

__device__ __align__(16) __nv_bfloat16 d_Ahi[(size_t)MAXM * 128];
__device__ __align__(16) __nv_bfloat16 d_Bhi[(size_t)(MAXM + 128) * 128];
__device__ int   d_flag[MAXM];
__device__ int   d_cnt[64];
__device__ int   d_Nn;
__device__ float d_gpart[32 * 128];
__device__ float d_g[128];
__device__ float d_Epart[(size_t)NCHUNK * MAXM];
__device__ float d_rowloss[MAXM];
__device__ int   d_ctr1 = 0;
__device__ int   d_ctr2 = 0;
__device__ int   d_ctr3 = 0;

// ------------------------------ helpers ------------------------------------

__device__ __forceinline__ uint32_t s2u(const void* p) {
    uint32_t a;
    asm("{ .reg .u64 t; cvta.to.shared.u64 t, %1; cvt.u32.u64 %0, t; }"
        : "=r"(a) : "l"(p));
    return a;
}

__device__ __forceinline__ void cp16(uint32_t s, const void* g) {
    asm volatile("cp.async.cg.shared.global [%0], [%1], 16;" :: "r"(s), "l"(g));
}
#define CP_COMMIT() asm volatile("cp.async.commit_group;" ::: "memory")

__device__ __forceinline__ void ldsm4(uint32_t (&r)[4], uint32_t addr) {
    asm volatile("ldmatrix.sync.aligned.m8n8.x4.shared.b16 {%0,%1,%2,%3}, [%4];"
                 : "=r"(r[0]), "=r"(r[1]), "=r"(r[2]), "=r"(r[3]) : "r"(addr));
}

__device__ __forceinline__ void mma16816(float (&d)[4], const uint32_t (&a)[4],
                                         uint32_t b0, uint32_t b1) {
    asm volatile(
        "mma.sync.aligned.m16n8k16.row.col.f32.bf16.bf16.f32 "
        "{%0,%1,%2,%3}, {%4,%5,%6,%7}, {%8,%9}, {%0,%1,%2,%3};"
        : "+f"(d[0]), "+f"(d[1]), "+f"(d[2]), "+f"(d[3])
        : "r"(a[0]), "r"(a[1]), "r"(a[2]), "r"(a[3]), "r"(b0), "r"(b1));
}

// XOR-swizzled smem tile: 128 rows x 256B row (16 x 16B chunks).
__device__ __forceinline__ uint32_t swz(uint32_t base, int row, int kchunk) {
    return base + row * 256 + (((uint32_t)(kchunk ^ (row & 7))) << 4);
}

__device__ __forceinline__ float ex2f(float t) {
    float r;
    asm("ex2.approx.f32 %0, %1;" : "=f"(r) : "f"(t));
    return r;
}

// exp on the FMA pipe (finalize only), rel err ~1.5e-7.
__device__ __forceinline__ float fexp(float x) {
    float t = x * 1.4426950408889634f;
    float z = t + 12582912.0f;
    int   ki = __float_as_int(z) - 0x4B400000;
    float r = t - (z - 12582912.0f);
    float p =      1.5403530393381610e-4f;
    p = fmaf(p, r, 1.3333558146428443e-3f);
    p = fmaf(p, r, 9.6181291076284772e-3f);
    p = fmaf(p, r, 5.5504108664821580e-2f);
    p = fmaf(p, r, 2.4022650695910072e-1f);
    p = fmaf(p, r, 6.9314718055994531e-1f);
    p = fmaf(p, r, 1.0f);
    return __int_as_float(__float_as_int(p) + (ki << 23));
}

// ------------------------ prep: flags+convert+g -----------------------------
// 32 blocks x 256 threads; all co-resident -> grid spin is safe.
// Phase 1: flags + per-block novel counts -> d_cnt, counter arrive + spin.
// Phase 2: prefix -> compaction positions; bf16 convert A+B; g partials.
// Last block: g reduce, Nn, zero-pad B tail, reset counters.

__global__ void prep_kernel(const float* __restrict__ F,
                            const int* __restrict__ labels,
                            const int* __restrict__ plab, int M, int B) {
    __shared__ int sPL[128];
    __shared__ int sCnt[8];
    __shared__ int sOff[8];
    __shared__ int sBase;
    __shared__ int sPos[256];
    __shared__ int sLast;
    __shared__ float sg[16][128];

    int tid = threadIdx.x, lane = tid & 31, w = tid >> 5;
    int nblk = gridDim.x;
    if (tid < B) sPL[tid] = plab[tid];
    __syncthreads();

    int i = blockIdx.x * 256 + tid;
    int lab = labels[i];
    int hit = 0;
    #pragma unroll 4
    for (int b = 0; b < B; ++b) hit |= (lab == sPL[b]);
    int f = hit ^ 1;
    d_flag[i] = f;
    unsigned bal = __ballot_sync(0xffffffffu, f);
    int lanePre = __popc(bal & ((1u << lane) - 1u));
    if (lane == 0) sCnt[w] = __popc(bal);
    __syncthreads();
    if (tid == 0) {
        int s = 0;
        #pragma unroll
        for (int q = 0; q < 8; ++q) s += sCnt[q];
        d_cnt[blockIdx.x] = s;
        __threadfence();
        atomicAdd(&d_ctr1, 1);
        while (atomicAdd(&d_ctr1, 0) < nblk) { }
    }
    __syncthreads();
    __threadfence();

    // Prefix base from preceding blocks' counts.
    if (w == 0) {
        int v = (lane < blockIdx.x) ? __ldcg(&d_cnt[lane]) : 0;
        #pragma unroll
        for (int off = 16; off; off >>= 1)
            v += __shfl_xor_sync(0xffffffffu, v, off);
        if (lane == 0) sBase = v;
    }
    __syncthreads();
    if (tid == 0) {
        int run = sBase;
        #pragma unroll
        for (int q = 0; q < 8; ++q) { int t = sCnt[q]; sOff[q] = run; run += t; }
    }
    __syncthreads();
    sPos[tid] = f ? (sOff[w] + lanePre) : -1;
    __syncthreads();

    int r0 = blockIdx.x * 256;
    int kc = tid & 15;
    float gacc[8];
    #pragma unroll
    for (int q = 0; q < 8; ++q) gacc[q] = 0.f;

    #pragma unroll 4
    for (int sub = 0; sub < 16; ++sub) {
        int rl = sub * 16 + (tid >> 4);
        int row = r0 + rl;
        float4 v0 = *(const float4*)(F + (size_t)row * 128 + kc * 8);
        float4 v1 = *(const float4*)(F + (size_t)row * 128 + kc * 8 + 4);
        float av[8] = {v0.x, v0.y, v0.z, v0.w, v1.x, v1.y, v1.z, v1.w};
        union { __nv_bfloat16 h[8]; uint4 u; } ph;
        #pragma unroll
        for (int q = 0; q < 8; ++q) ph.h[q] = __float2bfloat16(av[q]);
        ((uint4*)d_Ahi)[(size_t)row * 16 + kc] = ph.u;
        int p = sPos[rl];
        if (p >= 0) {
            ((uint4*)d_Bhi)[(size_t)p * 16 + kc] = ph.u;
            #pragma unroll
            for (int q = 0; q < 8; ++q) gacc[q] += av[q];
        }
    }
    #pragma unroll
    for (int q = 0; q < 8; ++q) sg[tid >> 4][kc * 8 + q] = gacc[q];
    __syncthreads();
    if (tid < 128) {
        float s = 0.f;
        #pragma unroll
        for (int q = 0; q < 16; ++q) s += sg[q][tid];
        d_gpart[blockIdx.x * 128 + tid] = s;
    }

    // Last block finishes: g reduce + Nn + B pad + counter resets.
    __threadfence();
    __syncthreads();
    if (tid == 0) sLast = (atomicAdd(&d_ctr2, 1) == nblk - 1);
    __syncthreads();
    if (sLast) {
        if (tid < 128) {
            float tot = 0.f;
            #pragma unroll
            for (int b = 0; b < 32; ++b) tot += __ldcg(&d_gpart[b * 128 + tid]);
            d_g[tid] = tot;
        }
        __shared__ int sNn;
        if (w == 0) {
            int v = __ldcg(&d_cnt[lane]);
            #pragma unroll
            for (int off = 16; off; off >>= 1)
                v += __shfl_xor_sync(0xffffffffu, v, off);
            if (lane == 0) { sNn = v; d_Nn = v; }
        }
        __syncthreads();
        int Nn = sNn;
        int Npad = (Nn + 127) & ~127;
        for (int idx = tid; idx < (Npad - Nn) * 16; idx += 256) {
            int row = Nn + (idx >> 4), c = idx & 15;
            ((uint4*)d_Bhi)[(size_t)row * 16 + c] = make_uint4(0, 0, 0, 0);
        }
        if (tid == 0) { d_ctr1 = 0; d_ctr2 = 0; }
    }
}

// ---------------------- main mma.sync exp-sum kernel -----------------------
// CTA: 128 rows x stream of 128-col novel tiles (stride NCHUNK).
// smem: A resident (32KB) + B double buffer (64KB) = 96KB; 2 CTAs/SM.
// 8 warps in 2x4 grid, warp tile 64x32, bf16 mma, MUFU exp.

__global__ __launch_bounds__(256, 2) void mma_expsum_kernel(int M) {
    extern __shared__ char dyn[];
    const uint32_t sbase = s2u(dyn);
    const uint32_t sA = sbase;
    const uint32_t sB[2] = {sbase + 32768, sbase + 65536};

    int tid = threadIdx.x;
    int lane = tid & 31, w = tid >> 5;
    int wr = w >> 2, wc = w & 3;               // warp grid 2 x 4
    int rowbase = blockIdx.x * 128;
    int chunk = blockIdx.y;
    int Nn = d_Nn;
    int ntiles = (Nn + 127) >> 7;
    int nt = (ntiles > chunk) ? ((ntiles - chunk + NCHUNK - 1) / NCHUNK) : 0;

    // Prologue: A (group 0, with B0) + B1 (group 1).
    {
        const char* ga = (const char*)d_Ahi + (size_t)blockIdx.x * 32768;
        #pragma unroll
        for (int it = 0; it < 8; ++it) {
            int c = it * 256 + tid;
            cp16(swz(sA, c >> 4, c & 15), ga + (size_t)c * 16);
        }
        if (nt > 0) {
            const char* gb = (const char*)d_Bhi + (size_t)chunk * 32768;
            #pragma unroll
            for (int it = 0; it < 8; ++it) {
                int c = it * 256 + tid;
                cp16(swz(sB[0], c >> 4, c & 15), gb + (size_t)c * 16);
            }
        }
        CP_COMMIT();
        if (nt > 1) {
            const char* gb = (const char*)d_Bhi + (size_t)(chunk + NCHUNK) * 32768;
            #pragma unroll
            for (int it = 0; it < 8; ++it) {
                int c = it * 256 + tid;
                cp16(swz(sB[1], c >> 4, c & 15), gb + (size_t)c * 16);
            }
            CP_COMMIT();
        }
    }

    int rl = lane & 15;                 // ldmatrix row within 16-row group
    int khalf = lane >> 4;              // +1 k-chunk for upper half
    float rs[8];
    #pragma unroll
    for (int q = 0; q < 8; ++q) rs[q] = 0.f;

    for (int k = 0; k < nt; ++k) {
        int p = k & 1;
        if (k + 1 < nt) asm volatile("cp.async.wait_group 1;" ::: "memory");
        else            asm volatile("cp.async.wait_group 0;" ::: "memory");
        __syncthreads();

        float acc[4][4][4];
        #pragma unroll
        for (int mi = 0; mi < 4; ++mi)
            #pragma unroll
            for (int ni = 0; ni < 4; ++ni)
                #pragma unroll
                for (int q = 0; q < 4; ++q) acc[mi][ni][q] = 0.f;

        #pragma unroll
        for (int ks = 0; ks < 8; ++ks) {
            int kc = ks * 2 + khalf;
            uint32_t a[4][4], b[2][4];
            #pragma unroll
            for (int mi = 0; mi < 4; ++mi)
                ldsm4(a[mi], swz(sA, wr * 64 + mi * 16 + rl, kc));
            #pragma unroll
            for (int n2 = 0; n2 < 2; ++n2)
                ldsm4(b[n2], swz(sB[p], wc * 32 + n2 * 16 + rl, kc));
            #pragma unroll
            for (int mi = 0; mi < 4; ++mi)
                #pragma unroll
                for (int ni = 0; ni < 4; ++ni) {
                    int n2 = ni >> 1, pr = ni & 1;
                    mma16816(acc[mi][ni], a[mi], b[n2][pr], b[n2][pr + 2]);
                }
        }

        // Register-only exp epilogue before the barrier.
        int cwarp = (chunk + k * NCHUNK) * 128 + wc * 32;
        if (cwarp + 32 <= Nn) {
            #pragma unroll
            for (int mi = 0; mi < 4; ++mi)
                #pragma unroll
                for (int ni = 0; ni < 4; ++ni) {
                    rs[mi * 2 + 0] += ex2f(acc[mi][ni][0] * LOG2E5) +
                                      ex2f(acc[mi][ni][1] * LOG2E5);
                    rs[mi * 2 + 1] += ex2f(acc[mi][ni][2] * LOG2E5) +
                                      ex2f(acc[mi][ni][3] * LOG2E5);
                }
        } else {
            #pragma unroll
            for (int mi = 0; mi < 4; ++mi)
                #pragma unroll
                for (int ni = 0; ni < 4; ++ni) {
                    int c0 = cwarp + ni * 8 + (lane & 3) * 2;
                    float t0 = (c0     < Nn) ? acc[mi][ni][0] * LOG2E5 : -1e30f;
                    float t1 = (c0 + 1 < Nn) ? acc[mi][ni][1] * LOG2E5 : -1e30f;
                    float t2 = (c0     < Nn) ? acc[mi][ni][2] * LOG2E5 : -1e30f;
                    float t3 = (c0 + 1 < Nn) ? acc[mi][ni][3] * LOG2E5 : -1e30f;
                    rs[mi * 2 + 0] += ex2f(t0) + ex2f(t1);
                    rs[mi * 2 + 1] += ex2f(t2) + ex2f(t3);
                }
        }

        __syncthreads();

        if (k + 2 < nt) {                   // prefetch B(k+2) into buffer p
            const char* gb = (const char*)d_Bhi +
                             (size_t)(chunk + (k + 2) * NCHUNK) * 32768;
            #pragma unroll
            for (int it = 0; it < 8; ++it) {
                int c = it * 256 + tid;
                cp16(swz(sB[p], c >> 4, c & 15), gb + (size_t)c * 16);
            }
            CP_COMMIT();
        }
    }

    // Quad reduce (lanes sharing a row), then cross-warp-col reduce in smem.
    #pragma unroll
    for (int q = 0; q < 8; ++q) {
        rs[q] += __shfl_xor_sync(0xffffffffu, rs[q], 1);
        rs[q] += __shfl_xor_sync(0xffffffffu, rs[q], 2);
    }
    __syncthreads();
    float* sred = (float*)dyn;              // 128 rows x 4 warp-cols
    if ((lane & 3) == 0) {
        int g = lane >> 2;
        #pragma unroll
        for (int mi = 0; mi < 4; ++mi)
            #pragma unroll
            for (int r8 = 0; r8 < 2; ++r8) {
                int row = wr * 64 + mi * 16 + r8 * 8 + g;
                sred[row * 4 + wc] = rs[mi * 2 + r8];
            }
    }
    __syncthreads();
    if (tid < 128) {
        float s = sred[tid * 4] + sred[tid * 4 + 1] +
                  sred[tid * 4 + 2] + sred[tid * 4 + 3];
        d_Epart[(size_t)chunk * M + rowbase + tid] = s;
    }
}

// --------------------- finalize + fused final reduce -----------------------
// 1024 threads, 32 rows per block; the last finishing block sums all row
// losses in a fixed order and writes the output.

__global__ void finalize_kernel(const float* __restrict__ F,
                                const float* __restrict__ protos,
                                const int* __restrict__ labels,
                                float* __restrict__ out, int M, int B) {
    extern __shared__ float sP[];          // B*129 floats
    __shared__ float fR[32][128];
    __shared__ float sm[1024];
    __shared__ int sLastF;
    int tid = threadIdx.x, lane = tid & 31, w = tid >> 5;

    for (int idx = tid; idx < B * 128; idx += 1024) {
        int b = idx >> 7, k = idx & 127;
        sP[b * 129 + k] = protos[idx];
    }
    int i = blockIdx.x * 32 + w;
    {
        float4 v = *(const float4*)(F + (size_t)i * 128 + lane * 4);
        *(float4*)&fR[w][lane * 4] = v;
    }
    __syncthreads();

    float dg = 0.f, ds = 0.f;
    #pragma unroll
    for (int q = 0; q < 4; ++q) {
        float fv = fR[w][lane * 4 + q];
        dg = fmaf(fv, d_g[lane * 4 + q], dg);
        ds = fmaf(fv, fv, ds);
    }

    float psum = 0.f, pexp = 0.f, bipi = 0.f;
    int lab = labels[i];
    #pragma unroll
    for (int pb = 0; pb < 4; ++pb) {
        int b = lane + pb * 32;
        if (b < B) {
            float d = 0.f;
            #pragma unroll 8
            for (int k = 0; k < 128; ++k)
                d = fmaf(fR[w][k], sP[b * 129 + k], d);
            float P = d * 5.0f;
            psum += P;
            pexp += fexp(P);
            if (b == lab) bipi = P;
        }
    }
    #pragma unroll
    for (int off = 16; off; off >>= 1) {
        dg   += __shfl_xor_sync(0xffffffffu, dg, off);
        ds   += __shfl_xor_sync(0xffffffffu, ds, off);
        psum += __shfl_xor_sync(0xffffffffu, psum, off);
        pexp += __shfl_xor_sync(0xffffffffu, pexp, off);
        bipi += __shfl_xor_sync(0xffffffffu, bipi, off);
    }

    if (lane == 0) {
        float E = 0.f;
        #pragma unroll
        for (int c = 0; c < NCHUNK; ++c) E += d_Epart[(size_t)c * M + i];
        float loss;
        if (d_flag[i]) {
            float Sii = ds * 5.0f;
            float den = (E - fexp(Sii)) + psum;
            int cnt = d_Nn - 1;
            if (cnt > 0) {
                float sumS = dg * 5.0f - Sii;
                loss = -((sumS - logf(den) * (float)cnt) / (float)cnt);
            } else {
                loss = 0.f;
            }
        } else {
            loss = -(bipi - logf(E + pexp));
        }
        d_rowloss[i] = loss;
    }

    // Fused final reduce by the last finishing block (fixed order).
    __threadfence();
    __syncthreads();
    if (tid == 0) sLastF = (atomicAdd(&d_ctr3, 1) == (int)gridDim.x - 1);
    __syncthreads();
    if (sLastF) {
        float s = 0.f;
        for (int r = tid; r < M; r += 1024) s += __ldcg(&d_rowloss[r]);
        sm[tid] = s;
        __syncthreads();
        for (int off = 512; off; off >>= 1) {
            if (tid < off) sm[tid] += sm[tid + off];
            __syncthreads();
        }
        if (tid == 0) { out[0] = sm[0] / (float)M; d_ctr3 = 0; }
    }
}

// ------------------------------- launcher ----------------------------------

extern "C" void kernel_launch(void* const* d_in, const int* in_sizes, int n_in,
                              void* d_out, int out_size) {
    const float* F      = (const float*)d_in[0];
    const int*   labels = (const int*)d_in[1];
    const float* protos = (const float*)d_in[2];
    const int*   plab   = (const int*)d_in[3];
    int M = in_sizes[1];                  // 8192
    int B = in_sizes[3];                  // 100
    int nblk = M / 256;                   // 32

    prep_kernel<<<nblk, 256>>>(F, labels, plab, M, B);

    size_t smemMain = 98304;              // 96 KB -> 2 CTAs/SM
    cudaFuncSetAttribute(mma_expsum_kernel,
                         cudaFuncAttributeMaxDynamicSharedMemorySize,
                         (int)smemMain);
    mma_expsum_kernel<<<dim3(M / 128, NCHUNK), 256, smemMain>>>(M);

    size_t smemP = (size_t)B * 129 * sizeof(float);
    cudaFuncSetAttribute(finalize_kernel,
                         cudaFuncAttributeMaxDynamicSharedMemorySize,
                         (int)smemP);
    finalize_kernel<<<M / 32, 1024, smemP>>>(F, protos, labels,
                                             (float*)d_out, M, B);
}